// round 5
// baseline (speedup 1.0000x reference)
#include <cuda_runtime.h>

// TSModel: 2-layer LSTM recurrence (layer0: 1->64, layer1: 64->1; layer1 input
// is c0, per-step output is c1). B=2048, T=1024, fp32.
//
// R4: 2-gates-per-thread restructure. 293 CTAs x 128 threads, MROWS=7.
// Thread t owns gate rows t and t+128 (weights in 128 packed-f32x2 regs), so
// each LDS.128 of h feeds 4 fma.rn.f32x2 -> per-SM shared traffic halves vs
// the 256-thread/1-gate layout (which ncu showed L1=77%, the binding pipe).

#define BATCH 2048
#define TSTEPS 1024
#define UNITS 64
#define GATES 256
#define MROWS 7
#define NCTA ((BATCH + MROWS - 1) / MROWS)   // 293
#define NTHR 128

typedef unsigned long long u64;

__device__ __forceinline__ u64 pack2(float lo, float hi) {
    u64 r;
    asm("mov.b64 %0, {%1, %2};" : "=l"(r) : "f"(lo), "f"(hi));
    return r;
}
__device__ __forceinline__ void unpack2(u64 v, float& lo, float& hi) {
    asm("mov.b64 {%0, %1}, %2;" : "=f"(lo), "=f"(hi) : "l"(v));
}
__device__ __forceinline__ u64 fma2(u64 a, u64 b, u64 c) {
    u64 d;
    asm("fma.rn.f32x2 %0, %1, %2, %3;" : "=l"(d) : "l"(a), "l"(b), "l"(c));
    return d;
}
__device__ __forceinline__ float rcp_apx(float x) {
    float r;
    asm("rcp.approx.f32 %0, %1;" : "=f"(r) : "f"(x));
    return r;
}
// sigmoid(x) = 1 / (1 + e^-x)
__device__ __forceinline__ float sig_f(float x) {
    return rcp_apx(1.0f + __expf(-x));
}
// tanh(x) = 1 - 2/(1 + e^{2x})
__device__ __forceinline__ float tanh_f(float x) {
    return fmaf(-2.0f, rcp_apx(1.0f + __expf(x + x)), 1.0f);
}

__global__ void __launch_bounds__(NTHR, 2)
lstm_kernel(const float* __restrict__ in,
            const float* __restrict__ Wih0, const float* __restrict__ Whh0,
            const float* __restrict__ bih0, const float* __restrict__ bhh0,
            const float* __restrict__ Wih1, const float* __restrict__ Whh1,
            const float* __restrict__ bih1, const float* __restrict__ bhh1,
            float* __restrict__ out) {
    __shared__ __align__(16) float Hs[MROWS][UNITS];
    __shared__ __align__(16) float Cs[MROWS][UNITS];
    __shared__ __align__(16) float Gs[MROWS][GATES];
    __shared__ __align__(16) float Xs[MROWS][TSTEPS];

    const int tid = threadIdx.x;
    const int r0 = blockIdx.x * MROWS;
    const int mrows = min(MROWS, BATCH - r0);

    // ---- one-time setup ----
    // Thread tid owns gate rows g0 = tid and g1 = tid + 128.
    u64 w0[32], w1[32];
    {
        const float2* wr0 = (const float2*)(Whh0 + tid * UNITS);
        const float2* wr1 = (const float2*)(Whh0 + (tid + 128) * UNITS);
#pragma unroll
        for (int k = 0; k < 32; k++) {
            float2 a = wr0[k];
            float2 b = wr1[k];
            w0[k] = pack2(a.x, a.y);
            w1[k] = pack2(b.x, b.y);
        }
    }
    const float wx0 = Wih0[tid];
    const float wx1 = Wih0[tid + 128];
    const float bs0 = bih0[tid] + bhh0[tid];
    const float bs1 = bih0[tid + 128] + bhh0[tid + 128];

    const int lane = tid & 31;
    const int wid = tid >> 5;                 // 0..3
    // Layer-1: lane l handles gate (l&3), slot (l>>2); 8 elems per lane.
    const int g1i = lane & 3;
    const int s1 = lane >> 2;
    float wi1[8];
#pragma unroll
    for (int k = 0; k < 8; k++) wi1[k] = Wih1[g1i * UNITS + s1 + 8 * k];
    const float whh1g = Whh1[g1i];
    const float b1g = bih1[g1i] + bhh1[g1i];

    // Stage input rows into SMEM (coalesced float4 copy)
    {
        const float4* src = (const float4*)(in + (size_t)r0 * TSTEPS);
        float4* dst = (float4*)&Xs[0][0];
        const int n4 = mrows * (TSTEPS / 4);
        for (int i = tid; i < n4; i += NTHR) dst[i] = src[i];
    }
    // Zero recurrent state
    for (int i = tid; i < MROWS * UNITS; i += NTHR) {
        (&Hs[0][0])[i] = 0.0f;
        (&Cs[0][0])[i] = 0.0f;
    }
    // Layer-1 state: warp w owns rows w and w+4 (replicated across lanes)
    float h1a = 0.0f, c1a = 0.0f;
    float h1b = 0.0f, c1b = 0.0f;
    __syncthreads();

    // ---- time loop ----
    for (int t = 0; t < TSTEPS; t++) {
        // Phase A: gates for rows 0..mrows-1; each thread computes 2 gate rows.
        for (int m = 0; m < mrows; m++) {
            const float xv = Xs[m][t];
            u64 acc00 = pack2(fmaf(xv, wx0, bs0), 0.0f);
            u64 acc01 = 0ULL;
            u64 acc10 = pack2(fmaf(xv, wx1, bs1), 0.0f);
            u64 acc11 = 0ULL;
            const ulonglong2* hp = (const ulonglong2*)&Hs[m][0];
#pragma unroll
            for (int j = 0; j < 16; j++) {
                ulonglong2 hv = hp[j];        // LDS.128 broadcast, feeds 4 FMA2
                acc00 = fma2(w0[2 * j], hv.x, acc00);
                acc01 = fma2(w0[2 * j + 1], hv.y, acc01);
                acc10 = fma2(w1[2 * j], hv.x, acc10);
                acc11 = fma2(w1[2 * j + 1], hv.y, acc11);
            }
            float a, b, c, d;
            unpack2(acc00, a, b);
            unpack2(acc01, c, d);
            Gs[m][tid] = (a + b) + (c + d);
            unpack2(acc10, a, b);
            unpack2(acc11, c, d);
            Gs[m][tid + 128] = (a + b) + (c + d);
        }
        __syncthreads();

        // Phase B: per-unit activation + state update (tasks = mrows*64 = 448)
#pragma unroll
        for (int k = 0; k < 4; k++) {
            const int task = tid + k * NTHR;
            if (task < mrows * UNITS) {
                const int m = task >> 6;
                const int u = task & 63;
                const float gi = Gs[m][u];
                const float gf = Gs[m][u + 64];
                const float gg = Gs[m][u + 128];
                const float go = Gs[m][u + 192];
                const float cc = Cs[m][u];
                const float cn = sig_f(gf) * cc + sig_f(gi) * tanh_f(gg);
                const float hn = sig_f(go) * tanh_f(cn);
                Cs[m][u] = cn;
                Hs[m][u] = hn;
            }
        }
        __syncthreads();

        // Phase C: layer-1 (input = c0). Warp w owns rows w and w+4.
#pragma unroll
        for (int rr = 0; rr < 2; rr++) {
            const int m = wid + rr * 4;
            if (m < mrows) {
                float h1 = rr ? h1b : h1a;
                float c1 = rr ? c1b : c1a;
                float acc = 0.0f;
#pragma unroll
                for (int k = 0; k < 8; k++)
                    acc = fmaf(wi1[k], Cs[m][s1 + 8 * k], acc);
                acc += __shfl_xor_sync(0xffffffffu, acc, 4);
                acc += __shfl_xor_sync(0xffffffffu, acc, 8);
                acc += __shfl_xor_sync(0xffffffffu, acc, 16);
                acc += fmaf(whh1g, h1, b1g);
                const float gi = __shfl_sync(0xffffffffu, acc, 0);
                const float gf = __shfl_sync(0xffffffffu, acc, 1);
                const float gg = __shfl_sync(0xffffffffu, acc, 2);
                const float go = __shfl_sync(0xffffffffu, acc, 3);
                c1 = sig_f(gf) * c1 + sig_f(gi) * tanh_f(gg);
                h1 = sig_f(go) * tanh_f(c1);
                if (lane == 0) out[(size_t)(r0 + m) * TSTEPS + t] = c1;
                if (rr) { h1b = h1; c1b = c1; } else { h1a = h1; c1a = c1; }
            }
        }
        // No extra barrier: next Phase A only touches Hs/Xs/Gs ordered by the
        // post-B barrier; Phase-C Cs reads complete before the next iteration's
        // post-A barrier releases any thread into Phase B (which writes Cs).
    }
}

extern "C" void kernel_launch(void* const* d_in, const int* in_sizes, int n_in,
                              void* d_out, int out_size) {
    (void)in_sizes; (void)n_in; (void)out_size;
    lstm_kernel<<<NCTA, NTHR>>>(
        (const float*)d_in[0],  // input (2048,1024)
        (const float*)d_in[1],  // W_ih0 (256,1)
        (const float*)d_in[2],  // W_hh0 (256,64)
        (const float*)d_in[3],  // b_ih0 (256)
        (const float*)d_in[4],  // b_hh0 (256)
        (const float*)d_in[5],  // W_ih1 (4,64)
        (const float*)d_in[6],  // W_hh1 (4,1)
        (const float*)d_in[7],  // b_ih1 (4)
        (const float*)d_in[8],  // b_hh1 (4)
        (float*)d_out);         // out (2048,1024)
}